// round 10
// baseline (speedup 1.0000x reference)
#include <cuda_runtime.h>
#include <cstdint>

// ---------------- problem constants ----------------
#define N_DOWN  16384
#define M1 65536              // rows of x_down / y / z
#define M2 262144             // rows of x_up / out
#define BM 128
#define THREADS 256
#define GRID 444              // 3 CTAs per SM

// ---------------- smem layout (bytes, per stage: [A 16KB][W 16KB]) ----------------
#define STAGE 32768
#define OFFW  16384
#define OFFI  (2 * STAGE)         // 65536: 128 ints
#define OFFB  (OFFI + 512)        // 128 floats
#define SMEM_BYTES (OFFB + 512)   // 66560  (3 CTAs x 66560 = 199680 < 228KB)

// ---------------- device scratch ----------------
__device__ __align__(256) float g_y[(size_t)M1 * 128];   // rna(LReLU(x_down@Wlin+b))
__device__ __align__(256) float g_z[(size_t)M1 * 128];   // y @ Wfus_bot  (fp32)
__device__ __align__(256) float g_Wf1[32768];            // Wlin fragment-packed (K=256)
__device__ __align__(256) float g_Wt[16384];             // Wfus[k<128]  fragment-packed
__device__ __align__(256) float g_Wb[16384];             // Wfus[k>=128] fragment-packed
__device__ int g_idx[M2];

// ---------------- helpers ----------------
__device__ __forceinline__ float tf32_rna(float x) {
    unsigned u; asm("cvt.rna.tf32.f32 %0, %1;" : "=r"(u) : "f"(x));
    return __uint_as_float(u);
}
__device__ __forceinline__ uint32_t rna_u(float x) {
    unsigned u; asm("cvt.rna.tf32.f32 %0, %1;" : "=r"(u) : "f"(x));
    return u;
}
__device__ __forceinline__ float lrelu(float v) { return v > 0.f ? v : 0.1f * v; }

__device__ __forceinline__ uint32_t smem_u32(const void* p) {
    uint32_t a;
    asm("{ .reg .u64 t; cvta.to.shared.u64 t, %1; cvt.u32.u64 %0, t; }" : "=r"(a) : "l"(p));
    return a;
}
__device__ __forceinline__ void cpa16(uint32_t saddr, const void* g) {
    asm volatile("cp.async.cg.shared.global [%0], [%1], 16;" :: "r"(saddr), "l"(g));
}
#define CP_COMMIT() asm volatile("cp.async.commit_group;" ::: "memory")
#define CP_WAIT1()  asm volatile("cp.async.wait_group 1;" ::: "memory")

#define MMA_TF32(d, a, b0, b1)                                                     \
    asm volatile(                                                                  \
        "mma.sync.aligned.m16n8k8.row.col.f32.tf32.tf32.f32 "                      \
        "{%0,%1,%2,%3},{%4,%5,%6,%7},{%8,%9},{%0,%1,%2,%3};"                       \
        : "+f"((d)[0]), "+f"((d)[1]), "+f"((d)[2]), "+f"((d)[3])                   \
        : "r"((a)[0]), "r"((a)[1]), "r"((a)[2]), "r"((a)[3]), "r"(b0), "r"(b1))

// ---------------- prep kernels ----------------
// Fused dtype-detect + convert. Detection: each block ORs 256 "odd" 32-bit
// words from the FIRST HALF of the buffer (word index 2j+1, j < n_idx/2 —
// in-bounds under BOTH int64 and int32 layouts). int64 -> hi words all zero;
// int32 -> 256 random indices all zero with prob (2^-14)^256 ~ 0.
__global__ void k_convert(const void* __restrict__ p, int n_idx) {
    __shared__ unsigned red[256];
    const int i = blockIdx.x * blockDim.x + threadIdx.x;
    const int j = i & (M2 / 2 - 1);
    unsigned hi = ((const unsigned*)p)[2 * j + 1];
    red[threadIdx.x] = hi;
    __syncthreads();
    for (int s = 128; s > 0; s >>= 1) {
        if ((int)threadIdx.x < s) red[threadIdx.x] |= red[threadIdx.x + s];
        __syncthreads();
    }
    const int is64 = (red[0] == 0u);
    if (i >= n_idx) return;
    int v = is64 ? (int)((const long long*)p)[i] : ((const int*)p)[i];
    g_idx[i] = (i >> 16) * N_DOWN + v;   // batch = i / 65536
}

// Fragment packing (identical mapping to the working R4-R8 kernels)
__global__ void k_prep_w(const float* __restrict__ Wlin, const float* __restrict__ Wfus) {
    int i = blockIdx.x * blockDim.x + threadIdx.x;   // 0..32767
    int e = i & 3, lane = (i >> 2) & 31, q = (i >> 7) & 7, kk = i >> 10;
    int p = e >> 1, hb = e & 1;
    int n = (2 * q + p) * 8 + (lane >> 2);
    int k = kk * 8 + (lane & 3) + hb * 4;
    g_Wf1[i] = tf32_rna(Wlin[k * 128 + n]);
    if (i < 16384) {
        g_Wt[i] = tf32_rna(Wfus[k * 128 + n]);
        g_Wb[i] = tf32_rna(Wfus[(k + 128) * 128 + n]);
    }
}

// ---------------- persistent tf32 GEMMs (BM=128, 256 thr, 3 CTA/SM) ----------------
// MODE 0: g_y = rna(LReLU(x_down[65536,256] @ Wlin + b))             K=256
// MODE 2: g_z = g_y[65536,128] @ Wfus_bot                            K=128
// MODE 1: out = LReLU(x_up[262144,128] @ Wfus_top + b + gather(g_z)) K=128
template <int MODE>
__device__ __forceinline__ void issue_stage(char* smc, int buf, int c, int tid,
                                            const float* __restrict__ A0,
                                            const float* __restrict__ Wg, int rbase) {
    constexpr int KSTR = (MODE == 0) ? 256 : 128;
    const int row = tid >> 1, half = tid & 1;
    const float* base = (MODE == 2) ? (const float*)g_y : A0;
    const float* src = base + (size_t)(rbase + row) * KSTR + c * 32 + half * 16;
    uint32_t abuf = smem_u32(smc + buf * STAGE) + row * 128;
    const int cb = half * 4, sw = row & 7;
#pragma unroll
    for (int j = 0; j < 4; j++)
        cpa16(abuf + ((cb + j) ^ sw) * 16, src + j * 4);
    // W chunk: 16KB linear copy (fragment-packed, contiguous per chunk)
    uint32_t wbuf = smem_u32(smc + buf * STAGE + OFFW);
    const float* wsrc = Wg + c * 4096;
#pragma unroll
    for (int j = 0; j < 4; j++) {
        int ch = j * THREADS + tid;
        cpa16(wbuf + ch * 16, wsrc + ch * 4);
    }
}

template <int MODE>
__global__ void __launch_bounds__(THREADS, 3)
gemm_tf32(const float* __restrict__ A0, const float* __restrict__ bias,
          float* __restrict__ outp) {
    constexpr int NCH = (MODE == 0) ? 8 : 4;

    extern __shared__ char smc[];
    const int tid = threadIdx.x;
    const int lane = tid & 31, wid = tid >> 5;
    const int g = lane >> 2, t4 = lane & 3;
    const int mrow = (wid & 3) * 32;          // warp tile 32x64 (4x2 warp grid)
    const int ncol = (wid >> 2) * 64;
    const int qbase = ncol >> 4;

    const float* Wg = (MODE == 0) ? g_Wf1 : ((MODE == 1) ? g_Wt : g_Wb);
    float* out = (MODE == 0) ? g_y : ((MODE == 2) ? g_z : outp);
    const int ntiles = ((MODE == 1) ? M2 : M1) / BM;

    if (MODE != 2 && tid < 128) ((float*)(smc + OFFB))[tid] = bias[tid];

    for (int t = blockIdx.x; t < ntiles; t += GRID) {
        const int rbase = t * BM;
        if (MODE == 1 && tid < BM) ((int*)(smc + OFFI))[tid] = g_idx[rbase + tid];

        issue_stage<MODE>(smc, 0, 0, tid, A0, Wg, rbase); CP_COMMIT();
        issue_stage<MODE>(smc, 1, 1, tid, A0, Wg, rbase); CP_COMMIT();

        float acc[2][8][4];
#pragma unroll
        for (int mt = 0; mt < 2; mt++)
#pragma unroll
            for (int nt = 0; nt < 8; nt++)
#pragma unroll
                for (int e = 0; e < 4; e++) acc[mt][nt][e] = 0.f;

#pragma unroll 1
        for (int c = 0; c < NCH; ++c) {
            CP_WAIT1();            // stage c landed (most recent commit is c+1)
            __syncthreads();       // visible everywhere

            const char* ab = smc + (c & 1) * STAGE;
            const char* wb = ab + OFFW;
#pragma unroll
            for (int ks = 0; ks < 4; ks++) {
                uint32_t a[2][4];
#pragma unroll
                for (int mt = 0; mt < 2; mt++) {
                    const char* base = ab + (mrow + mt * 16 + g) * 128 + t4 * 4;
                    const int c0 = ((2 * ks) ^ g) * 16;
                    const int c1 = ((2 * ks + 1) ^ g) * 16;
                    if (MODE == 2) {    // g_y already exact tf32 -> skip cvt
                        a[mt][0] = *(const uint32_t*)(base + c0);
                        a[mt][1] = *(const uint32_t*)(base + 8 * 128 + c0);
                        a[mt][2] = *(const uint32_t*)(base + c1);
                        a[mt][3] = *(const uint32_t*)(base + 8 * 128 + c1);
                    } else {
                        a[mt][0] = rna_u(*(const float*)(base + c0));
                        a[mt][1] = rna_u(*(const float*)(base + 8 * 128 + c0));
                        a[mt][2] = rna_u(*(const float*)(base + c1));
                        a[mt][3] = rna_u(*(const float*)(base + 8 * 128 + c1));
                    }
                }
                uint4 bq[4];
#pragma unroll
                for (int i = 0; i < 4; i++)
                    bq[i] = *(const uint4*)(wb + ((ks * 8 + qbase + i) * 32 + lane) * 16);
#pragma unroll
                for (int mt = 0; mt < 2; mt++) {
#pragma unroll
                    for (int nt = 0; nt < 8; nt++) {
                        uint32_t b0 = (nt & 1) ? bq[nt >> 1].z : bq[nt >> 1].x;
                        uint32_t b1 = (nt & 1) ? bq[nt >> 1].w : bq[nt >> 1].y;
                        MMA_TF32(acc[mt][nt], a[mt], b0, b1);
                    }
                }
            }

            __syncthreads();       // all reads of buf (c&1) done
            if (c + 2 < NCH)
                issue_stage<MODE>(smc, c & 1, c + 2, tid, A0, Wg, rbase);
            CP_COMMIT();           // always commit (uniform group counting)
        }

        // ---------------- epilogue ----------------
        if (MODE == 2) {
#pragma unroll
            for (int nt = 0; nt < 8; nt++) {
                const int col = ncol + nt * 8 + t4 * 2;
#pragma unroll
                for (int mt = 0; mt < 2; mt++) {
                    const int r0 = rbase + mrow + mt * 16 + g;
                    *(float2*)(out + (size_t)r0 * 128 + col) =
                        make_float2(acc[mt][nt][0], acc[mt][nt][1]);
                    *(float2*)(out + (size_t)(r0 + 8) * 128 + col) =
                        make_float2(acc[mt][nt][2], acc[mt][nt][3]);
                }
            }
        } else {
            const float* bs = (const float*)(smc + OFFB);
            int gr[2][2];
            if (MODE == 1) {
                const int* sI = (const int*)(smc + OFFI);
#pragma unroll
                for (int mt = 0; mt < 2; mt++) {
                    gr[mt][0] = sI[mrow + mt * 16 + g];
                    gr[mt][1] = sI[mrow + mt * 16 + g + 8];
                }
            }
#pragma unroll
            for (int nt = 0; nt < 8; nt++) {
                const int col = ncol + nt * 8 + t4 * 2;
                const float b0 = bs[col], b1 = bs[col + 1];
#pragma unroll
                for (int mt = 0; mt < 2; mt++) {
                    const int r0 = rbase + mrow + mt * 16 + g;
                    float2 v0, v1;
                    if (MODE == 1) {
                        float2 z0 = *(const float2*)(g_z + (size_t)gr[mt][0] * 128 + col);
                        float2 z1 = *(const float2*)(g_z + (size_t)gr[mt][1] * 128 + col);
                        v0.x = lrelu(acc[mt][nt][0] + b0 + z0.x);
                        v0.y = lrelu(acc[mt][nt][1] + b1 + z0.y);
                        v1.x = lrelu(acc[mt][nt][2] + b0 + z1.x);
                        v1.y = lrelu(acc[mt][nt][3] + b1 + z1.y);
                    } else {
                        v0.x = tf32_rna(lrelu(acc[mt][nt][0] + b0));
                        v0.y = tf32_rna(lrelu(acc[mt][nt][1] + b1));
                        v1.x = tf32_rna(lrelu(acc[mt][nt][2] + b0));
                        v1.y = tf32_rna(lrelu(acc[mt][nt][3] + b1));
                    }
                    *(float2*)(out + (size_t)r0 * 128 + col) = v0;
                    *(float2*)(out + (size_t)(r0 + 8) * 128 + col) = v1;
                }
            }
        }
        __syncthreads();   // protect buffers/sIdx before next tile's prologue
    }
}

// ---------------- launch ----------------
extern "C" void kernel_launch(void* const* d_in, const int* in_sizes, int n_in,
                              void* d_out, int out_size) {
    const float* x_down = (const float*)d_in[0];
    const float* x_up   = (const float*)d_in[1];
    const void*  up_idx = d_in[2];
    const float* Wlin   = (const float*)d_in[3];
    const float* blin   = (const float*)d_in[4];
    const float* bfus   = (const float*)d_in[6];
    float* out = (float*)d_out;

    cudaFuncSetAttribute(gemm_tf32<0>, cudaFuncAttributeMaxDynamicSharedMemorySize, SMEM_BYTES);
    cudaFuncSetAttribute(gemm_tf32<1>, cudaFuncAttributeMaxDynamicSharedMemorySize, SMEM_BYTES);
    cudaFuncSetAttribute(gemm_tf32<2>, cudaFuncAttributeMaxDynamicSharedMemorySize, SMEM_BYTES);

    k_convert<<<M2 / 256, 256>>>(up_idx, M2);                    // launch 1 (fused detect)
    k_prep_w<<<32768 / 256, 256>>>(Wlin, (const float*)d_in[5]); // launch 2

    gemm_tf32<0><<<GRID, THREADS, SMEM_BYTES>>>(x_down, blin, nullptr);     // launch 3
    gemm_tf32<2><<<GRID, THREADS, SMEM_BYTES>>>(nullptr, nullptr, nullptr); // launch 4 (profiled)
    gemm_tf32<1><<<GRID, THREADS, SMEM_BYTES>>>(x_up, bfus, out);           // launch 5
}

// round 13
// speedup vs baseline: 2.0726x; 2.0726x over previous
#include <cuda_runtime.h>
#include <cstdint>

// ---------------- problem constants ----------------
#define N_DOWN  16384
#define M1 65536              // rows of x_down / y / z
#define M2 262144             // rows of x_up / out
#define BM 128
#define THREADS 256
#define GRID 296              // 2 CTAs per SM

// ---------------- device scratch ----------------
__device__ __align__(256) float g_y[(size_t)M1 * 128];   // rna(LReLU(x_down@Wlin+b))
__device__ __align__(256) float g_z[(size_t)M1 * 128];   // y @ Wfus_bot  (fp32)
__device__ __align__(256) float g_Wf1[32768];            // Wlin fragment-packed (K=256)
__device__ __align__(256) float g_Wt[16384];             // Wfus[k<128]  fragment-packed
__device__ __align__(256) float g_Wb[16384];             // Wfus[k>=128] fragment-packed
__device__ int g_idx[M2];

// ---------------- helpers ----------------
__device__ __forceinline__ float tf32_rna(float x) {
    unsigned u; asm("cvt.rna.tf32.f32 %0, %1;" : "=r"(u) : "f"(x));
    return __uint_as_float(u);
}
__device__ __forceinline__ uint32_t rna_u(float x) {
    unsigned u; asm("cvt.rna.tf32.f32 %0, %1;" : "=r"(u) : "f"(x));
    return u;
}
__device__ __forceinline__ float lrelu(float v) { return v > 0.f ? v : 0.1f * v; }

__device__ __forceinline__ uint32_t smem_u32(const void* p) {
    uint32_t a;
    asm("{ .reg .u64 t; cvta.to.shared.u64 t, %1; cvt.u32.u64 %0, t; }" : "=r"(a) : "l"(p));
    return a;
}
__device__ __forceinline__ void cpa16(uint32_t saddr, const void* g) {
    asm volatile("cp.async.cg.shared.global [%0], [%1], 16;" :: "r"(saddr), "l"(g));
}
#define CP_COMMIT() asm volatile("cp.async.commit_group;" ::: "memory")
#define CP_WAIT1()  asm volatile("cp.async.wait_group 1;" ::: "memory")

#define MMA_TF32(d, a, b0, b1)                                                     \
    asm volatile(                                                                  \
        "mma.sync.aligned.m16n8k8.row.col.f32.tf32.tf32.f32 "                      \
        "{%0,%1,%2,%3},{%4,%5,%6,%7},{%8,%9},{%0,%1,%2,%3};"                       \
        : "+f"((d)[0]), "+f"((d)[1]), "+f"((d)[2]), "+f"((d)[3])                   \
        : "r"((a)[0]), "r"((a)[1]), "r"((a)[2]), "r"((a)[3]), "r"(b0), "r"(b1))

// ---------------- merged prep kernel ----------------
// Blocks 0..1023: idx convert with fused dtype detection (per-block OR of 256
// odd words from the first half -- in-bounds under both layouts; int64 -> all
// zero, int32 -> nonzero with overwhelming probability).
// Blocks 1024..1151: fragment-pack all weights (mapping identical to R4-R8).
__global__ void k_prep(const void* __restrict__ p,
                       const float* __restrict__ Wlin,
                       const float* __restrict__ Wfus) {
    const int b = blockIdx.x;
    if (b < 1024) {
        __shared__ unsigned red[256];
        const int i = b * 256 + threadIdx.x;
        const int j = i & (M2 / 2 - 1);
        red[threadIdx.x] = ((const unsigned*)p)[2 * j + 1];
        __syncthreads();
        for (int s = 128; s > 0; s >>= 1) {
            if ((int)threadIdx.x < s) red[threadIdx.x] |= red[threadIdx.x + s];
            __syncthreads();
        }
        const int is64 = (red[0] == 0u);
        int v = is64 ? (int)((const long long*)p)[i] : ((const int*)p)[i];
        g_idx[i] = (i >> 16) * N_DOWN + v;   // batch = i / 65536
    } else {
        int i = (b - 1024) * 256 + threadIdx.x;   // 0..32767
        int e = i & 3, lane = (i >> 2) & 31, q = (i >> 7) & 7, kk = i >> 10;
        int pp = e >> 1, hb = e & 1;
        int n = (2 * q + pp) * 8 + (lane >> 2);
        int k = kk * 8 + (lane & 3) + hb * 4;
        g_Wf1[i] = tf32_rna(Wlin[k * 128 + n]);
        if (i < 16384) {
            g_Wt[i] = tf32_rna(Wfus[k * 128 + n]);
            g_Wb[i] = tf32_rna(Wfus[(k + 128) * 128 + n]);
        }
    }
}

// ---------------- persistent tf32 GEMMs ----------------
// MODE 0: g_y = rna(LReLU(x_down[65536,256] @ Wlin + b))             K=256, streamed W
// MODE 2: g_z = g_y[65536,128] @ Wfus_bot                            K=128, resident W
// MODE 1: out = LReLU(x_up[262144,128] @ Wfus_top + b + gather(g_z)) K=128, resident W
//
// Smem layouts (bytes):
//  MODE 0:  3 stages of [A 16KB | W 16KB] -> 98304; idx 512; bias 512 = 99328
//  MODE1/2: W 65536 resident; 3 A stages 49152; idx 512; bias 512   = 115712
#define STG0   32768
#define STG12  16384
#define OFFA12 65536

template <int MODE>
__device__ __forceinline__ void issue_stage(char* smc, int buf, int c, int tid,
                                            const float* __restrict__ A0,
                                            const float* __restrict__ Wg, int rbase) {
    constexpr int KSTR = (MODE == 0) ? 256 : 128;
    const int row = tid >> 1, half = tid & 1;
    const float* base = (MODE == 2) ? (const float*)g_y : A0;
    const float* src = base + (size_t)(rbase + row) * KSTR + c * 32 + half * 16;
    uint32_t abuf = (MODE == 0)
        ? smem_u32(smc) + buf * STG0 + row * 128
        : smem_u32(smc) + OFFA12 + buf * STG12 + row * 128;
    const int cb = half * 4, sw = row & 7;
#pragma unroll
    for (int j = 0; j < 4; j++)
        cpa16(abuf + ((cb + j) ^ sw) * 16, src + j * 4);
    if (MODE == 0) {   // stream 16KB W chunk alongside A
        uint32_t wbuf = smem_u32(smc) + buf * STG0 + 16384;
        const float* wsrc = Wg + c * 4096;
#pragma unroll
        for (int j = 0; j < 4; j++) {
            int ch = j * THREADS + tid;
            cpa16(wbuf + ch * 16, wsrc + ch * 4);
        }
    }
}

template <int MODE>
__global__ void __launch_bounds__(THREADS, 2)
gemm_tf32(const float* __restrict__ A0, const float* __restrict__ bias,
          float* __restrict__ outp) {
    constexpr int NCH  = (MODE == 0) ? 8 : 4;
    constexpr int OFFI = (MODE == 0) ? 3 * STG0 : OFFA12 + 3 * STG12;
    constexpr int OFFB = OFFI + 512;

    extern __shared__ char smc[];
    const int tid = threadIdx.x;
    const int lane = tid & 31, wid = tid >> 5;
    const int g = lane >> 2, t4 = lane & 3;
    const int mrow = (wid & 3) * 32;          // warp tile 32x64 (4x2 warp grid)
    const int ncol = (wid >> 2) * 64;
    const int qbase = ncol >> 4;

    const float* Wg = (MODE == 0) ? g_Wf1 : ((MODE == 1) ? g_Wt : g_Wb);
    float* out = (MODE == 0) ? g_y : ((MODE == 2) ? g_z : outp);
    const int ntiles = ((MODE == 1) ? M2 : M1) / BM;

    // resident W for modes 1/2 (64KB, one linear cp.async batch, group G0)
    if (MODE != 0) {
        uint32_t wdst = smem_u32(smc);
#pragma unroll
        for (int j = 0; j < 16; j++) {
            int ch = j * THREADS + tid;
            cpa16(wdst + ch * 16, Wg + ch * 4);
        }
    }
    CP_COMMIT();
    if (MODE != 2 && tid < 128) ((float*)(smc + OFFB))[tid] = bias[tid];

    for (int t = blockIdx.x; t < ntiles; t += GRID) {
        const int rbase = t * BM;
        if (MODE == 1 && tid < BM) ((int*)(smc + OFFI))[tid] = g_idx[rbase + tid];

        issue_stage<MODE>(smc, 0, 0, tid, A0, Wg, rbase); CP_COMMIT();
        issue_stage<MODE>(smc, 1, 1, tid, A0, Wg, rbase); CP_COMMIT();

        float acc[2][8][4];
#pragma unroll
        for (int mt = 0; mt < 2; mt++)
#pragma unroll
            for (int nt = 0; nt < 8; nt++)
#pragma unroll
                for (int e = 0; e < 4; e++) acc[mt][nt][e] = 0.f;

#pragma unroll 1
        for (int c = 0; c < NCH; ++c) {
            CP_WAIT1();            // stage c landed (newest commit is stage c+1)
            __syncthreads();       // visible everywhere; chunk c-1 reads all done
            if (c + 2 < NCH)       // buf (c+2)%3 == (c-1)%3, safe after sync
                issue_stage<MODE>(smc, (c + 2) % 3, c + 2, tid, A0, Wg, rbase);
            CP_COMMIT();           // uniform group counting

            const char* ab = (MODE == 0) ? smc + (c % 3) * STG0
                                         : smc + OFFA12 + (c % 3) * STG12;
            const char* wb = (MODE == 0) ? ab + 16384 : smc + c * 16384;
#pragma unroll
            for (int ks = 0; ks < 4; ks++) {
                uint32_t a[2][4];
#pragma unroll
                for (int mt = 0; mt < 2; mt++) {
                    const char* base = ab + (mrow + mt * 16 + g) * 128 + t4 * 4;
                    const int c0 = ((2 * ks) ^ g) * 16;
                    const int c1 = ((2 * ks + 1) ^ g) * 16;
                    if (MODE == 2) {    // g_y already exact tf32 -> skip cvt
                        a[mt][0] = *(const uint32_t*)(base + c0);
                        a[mt][1] = *(const uint32_t*)(base + 8 * 128 + c0);
                        a[mt][2] = *(const uint32_t*)(base + c1);
                        a[mt][3] = *(const uint32_t*)(base + 8 * 128 + c1);
                    } else {
                        a[mt][0] = rna_u(*(const float*)(base + c0));
                        a[mt][1] = rna_u(*(const float*)(base + 8 * 128 + c0));
                        a[mt][2] = rna_u(*(const float*)(base + c1));
                        a[mt][3] = rna_u(*(const float*)(base + 8 * 128 + c1));
                    }
                }
                uint4 bq[4];
#pragma unroll
                for (int i = 0; i < 4; i++)
                    bq[i] = *(const uint4*)(wb + ((ks * 8 + qbase + i) * 32 + lane) * 16);
#pragma unroll
                for (int mt = 0; mt < 2; mt++) {
#pragma unroll
                    for (int nt = 0; nt < 8; nt++) {
                        uint32_t b0 = (nt & 1) ? bq[nt >> 1].z : bq[nt >> 1].x;
                        uint32_t b1 = (nt & 1) ? bq[nt >> 1].w : bq[nt >> 1].y;
                        MMA_TF32(acc[mt][nt], a[mt], b0, b1);
                    }
                }
            }
        }

        // ---------------- epilogue ----------------
        if (MODE == 2) {
#pragma unroll
            for (int nt = 0; nt < 8; nt++) {
                const int col = ncol + nt * 8 + t4 * 2;
#pragma unroll
                for (int mt = 0; mt < 2; mt++) {
                    const int r0 = rbase + mrow + mt * 16 + g;
                    *(float2*)(out + (size_t)r0 * 128 + col) =
                        make_float2(acc[mt][nt][0], acc[mt][nt][1]);
                    *(float2*)(out + (size_t)(r0 + 8) * 128 + col) =
                        make_float2(acc[mt][nt][2], acc[mt][nt][3]);
                }
            }
        } else {
            const float* bs = (const float*)(smc + OFFB);
            int gr[2][2];
            if (MODE == 1) {
                const int* sI = (const int*)(smc + OFFI);
#pragma unroll
                for (int mt = 0; mt < 2; mt++) {
                    gr[mt][0] = sI[mrow + mt * 16 + g];
                    gr[mt][1] = sI[mrow + mt * 16 + g + 8];
                }
            }
#pragma unroll
            for (int nt = 0; nt < 8; nt++) {
                const int col = ncol + nt * 8 + t4 * 2;
                const float b0 = bs[col], b1 = bs[col + 1];
#pragma unroll
                for (int mt = 0; mt < 2; mt++) {
                    const int r0 = rbase + mrow + mt * 16 + g;
                    float2 v0, v1;
                    if (MODE == 1) {
                        float2 z0 = *(const float2*)(g_z + (size_t)gr[mt][0] * 128 + col);
                        float2 z1 = *(const float2*)(g_z + (size_t)gr[mt][1] * 128 + col);
                        v0.x = lrelu(acc[mt][nt][0] + b0 + z0.x);
                        v0.y = lrelu(acc[mt][nt][1] + b1 + z0.y);
                        v1.x = lrelu(acc[mt][nt][2] + b0 + z1.x);
                        v1.y = lrelu(acc[mt][nt][3] + b1 + z1.y);
                    } else {
                        v0.x = tf32_rna(lrelu(acc[mt][nt][0] + b0));
                        v0.y = tf32_rna(lrelu(acc[mt][nt][1] + b1));
                        v1.x = tf32_rna(lrelu(acc[mt][nt][2] + b0));
                        v1.y = tf32_rna(lrelu(acc[mt][nt][3] + b1));
                    }
                    *(float2*)(out + (size_t)r0 * 128 + col) = v0;
                    *(float2*)(out + (size_t)(r0 + 8) * 128 + col) = v1;
                }
            }
        }
        __syncthreads();   // protect buffers/sIdx before next tile's prologue
    }
}

// ---------------- launch ----------------
extern "C" void kernel_launch(void* const* d_in, const int* in_sizes, int n_in,
                              void* d_out, int out_size) {
    const float* x_down = (const float*)d_in[0];
    const float* x_up   = (const float*)d_in[1];
    const void*  up_idx = d_in[2];
    const float* Wlin   = (const float*)d_in[3];
    const float* blin   = (const float*)d_in[4];
    const float* bfus   = (const float*)d_in[6];
    float* out = (float*)d_out;

    constexpr int SM0  = 3 * STG0 + 512 + 512;            //  99328
    constexpr int SM12 = OFFA12 + 3 * STG12 + 512 + 512;  // 115712

    cudaFuncSetAttribute(gemm_tf32<0>, cudaFuncAttributeMaxDynamicSharedMemorySize, SM0);
    cudaFuncSetAttribute(gemm_tf32<1>, cudaFuncAttributeMaxDynamicSharedMemorySize, SM12);
    cudaFuncSetAttribute(gemm_tf32<2>, cudaFuncAttributeMaxDynamicSharedMemorySize, SM12);

    k_prep<<<1152, 256>>>(up_idx, Wlin, (const float*)d_in[5]);             // launch 1
    gemm_tf32<0><<<GRID, THREADS, SM0>>>(x_down, blin, nullptr);            // launch 2
    gemm_tf32<2><<<GRID, THREADS, SM12>>>(nullptr, nullptr, nullptr);       // launch 3
    gemm_tf32<1><<<GRID, THREADS, SM12>>>(x_up, bfus, out);                 // launch 4 (profiled)
}

// round 14
// speedup vs baseline: 2.3954x; 1.1558x over previous
#include <cuda_runtime.h>
#include <cuda_fp16.h>
#include <cstdint>

// ---------------- problem constants ----------------
#define N_DOWN  16384
#define M1 65536              // rows of x_down / y / z
#define M2 262144             // rows of x_up / out
#define BM 128
#define THREADS 256
#define GRID 296              // 2 CTAs per SM

// ---------------- device scratch ----------------
__device__ __align__(256) float  g_y[(size_t)M1 * 128];   // rna(LReLU(x_down@Wlin+b))
__device__ __align__(256) __half g_zh[(size_t)M1 * 128];  // y @ Wfus_bot  (fp16)
__device__ __align__(256) float  g_Wf1[32768];            // Wlin fragment-packed (K=256)
__device__ __align__(256) float  g_Wt[16384];             // Wfus[k<128]  fragment-packed
__device__ __align__(256) float  g_Wb[16384];             // Wfus[k>=128] fragment-packed
__device__ int g_idx[M2];

// smem geometry shared by modes 1/2
#define STG0   32768
#define STG12  16384
#define OFFA12 65536
#define OFFI12 (OFFA12 + 3 * STG12)     // 114688
#define OFFB12 (OFFI12 + 512)

// ---------------- helpers ----------------
__device__ __forceinline__ float tf32_rna(float x) {
    unsigned u; asm("cvt.rna.tf32.f32 %0, %1;" : "=r"(u) : "f"(x));
    return __uint_as_float(u);
}
__device__ __forceinline__ uint32_t rna_u(float x) {
    unsigned u; asm("cvt.rna.tf32.f32 %0, %1;" : "=r"(u) : "f"(x));
    return u;
}
__device__ __forceinline__ float lrelu(float v) { return v > 0.f ? v : 0.1f * v; }

__device__ __forceinline__ uint32_t smem_u32(const void* p) {
    uint32_t a;
    asm("{ .reg .u64 t; cvta.to.shared.u64 t, %1; cvt.u32.u64 %0, t; }" : "=r"(a) : "l"(p));
    return a;
}
__device__ __forceinline__ void cpa16(uint32_t saddr, const void* g) {
    asm volatile("cp.async.cg.shared.global [%0], [%1], 16;" :: "r"(saddr), "l"(g));
}
#define CP_COMMIT() asm volatile("cp.async.commit_group;" ::: "memory")
#define CP_WAIT1()  asm volatile("cp.async.wait_group 1;" ::: "memory")
#define CP_WAIT0()  asm volatile("cp.async.wait_group 0;" ::: "memory")

#define MMA_TF32(d, a, b0, b1)                                                     \
    asm volatile(                                                                  \
        "mma.sync.aligned.m16n8k8.row.col.f32.tf32.tf32.f32 "                      \
        "{%0,%1,%2,%3},{%4,%5,%6,%7},{%8,%9},{%0,%1,%2,%3};"                       \
        : "+f"((d)[0]), "+f"((d)[1]), "+f"((d)[2]), "+f"((d)[3])                   \
        : "r"((a)[0]), "r"((a)[1]), "r"((a)[2]), "r"((a)[3]), "r"(b0), "r"(b1))

// ---------------- merged prep kernel ----------------
__global__ void k_prep(const void* __restrict__ p,
                       const float* __restrict__ Wlin,
                       const float* __restrict__ Wfus) {
    const int b = blockIdx.x;
    if (b < 1024) {
        __shared__ unsigned red[256];
        const int i = b * 256 + threadIdx.x;
        const int j = i & (M2 / 2 - 1);
        red[threadIdx.x] = ((const unsigned*)p)[2 * j + 1];
        __syncthreads();
        for (int s = 128; s > 0; s >>= 1) {
            if ((int)threadIdx.x < s) red[threadIdx.x] |= red[threadIdx.x + s];
            __syncthreads();
        }
        const int is64 = (red[0] == 0u);
        int v = is64 ? (int)((const long long*)p)[i] : ((const int*)p)[i];
        g_idx[i] = (i >> 16) * N_DOWN + v;   // batch = i / 65536
    } else {
        int i = (b - 1024) * 256 + threadIdx.x;   // 0..32767
        int e = i & 3, lane = (i >> 2) & 31, q = (i >> 7) & 7, kk = i >> 10;
        int pp = e >> 1, hb = e & 1;
        int n = (2 * q + pp) * 8 + (lane >> 2);
        int k = kk * 8 + (lane & 3) + hb * 4;
        g_Wf1[i] = tf32_rna(Wlin[k * 128 + n]);
        if (i < 16384) {
            g_Wt[i] = tf32_rna(Wfus[k * 128 + n]);
            g_Wb[i] = tf32_rna(Wfus[(k + 128) * 128 + n]);
        }
    }
}

// ---------------- persistent tf32 GEMMs ----------------
// MODE 0: g_y  = rna(LReLU(x_down[65536,256] @ Wlin + b))              K=256, streamed W
// MODE 2: g_zh = f16(g_y[65536,128] @ Wfus_bot)                        K=128, resident W
// MODE 1: out  = LReLU(x_up[262144,128] @ Wfus_top + b + gather(g_zh)) K=128, resident W
template <int MODE>
__device__ __forceinline__ void issue_stage(char* smc, int buf, int c, int tid,
                                            const float* __restrict__ A0,
                                            const float* __restrict__ Wg, int rbase) {
    constexpr int KSTR = (MODE == 0) ? 256 : 128;
    const int row = tid >> 1, half = tid & 1;
    const float* base = (MODE == 2) ? (const float*)g_y : A0;
    const float* src = base + (size_t)(rbase + row) * KSTR + c * 32 + half * 16;
    uint32_t abuf = (MODE == 0)
        ? smem_u32(smc) + buf * STG0 + row * 128
        : smem_u32(smc) + OFFA12 + buf * STG12 + row * 128;
    const int cb = half * 4, sw = row & 7;
#pragma unroll
    for (int j = 0; j < 4; j++)
        cpa16(abuf + ((cb + j) ^ sw) * 16, src + j * 4);
    if (MODE == 0) {   // stream 16KB W chunk alongside A
        uint32_t wbuf = smem_u32(smc) + buf * STG0 + 16384;
        const float* wsrc = Wg + c * 4096;
#pragma unroll
        for (int j = 0; j < 4; j++) {
            int ch = j * THREADS + tid;
            cpa16(wbuf + ch * 16, wsrc + ch * 4);
        }
    }
}

// Prefetch 64 fp16 z-rows (rowbase..rowbase+63) into A buffer `buf` (16KB).
// 4 threads per row, 4x 16B chunks each; 32B-granule XOR swizzle vs (row&7).
__device__ __forceinline__ void issue_z(char* smc, int buf, int rowbase, int tid) {
    const int rr = tid >> 2;          // local row 0..63
    const int seg = tid & 3;          // 64B segment
    const int gr = ((const int*)(smc + OFFI12))[rowbase + rr];
    const char* src = (const char*)(g_zh + (size_t)gr * 128) + seg * 64;
    uint32_t base = smem_u32(smc) + OFFA12 + buf * STG12 + rr * 256;
    const int sw = rr & 7;
#pragma unroll
    for (int j = 0; j < 4; j++) {
        int c0 = seg * 4 + j;         // 16B chunk 0..15
        int u = (c0 >> 1) ^ sw;       // swizzled 32B unit
        cpa16(base + u * 32 + (c0 & 1) * 16, src + j * 16);
    }
}

template <int MODE>
__global__ void __launch_bounds__(THREADS, 2)
gemm_tf32(const float* __restrict__ A0, const float* __restrict__ bias,
          float* __restrict__ outp) {
    constexpr int NCH  = (MODE == 0) ? 8 : 4;
    constexpr int OFFI = (MODE == 0) ? 3 * STG0 : OFFI12;
    constexpr int OFFB = OFFI + 512;

    extern __shared__ char smc[];
    const int tid = threadIdx.x;
    const int lane = tid & 31, wid = tid >> 5;
    const int g = lane >> 2, t4 = lane & 3;
    const int mrow = (wid & 3) * 32;          // warp tile 32x64 (4x2 warp grid)
    const int ncol = (wid >> 2) * 64;
    const int qbase = ncol >> 4;

    const float* Wg = (MODE == 0) ? g_Wf1 : ((MODE == 1) ? g_Wt : g_Wb);
    float* out = (MODE == 0) ? g_y : outp;
    const int ntiles = ((MODE == 1) ? M2 : M1) / BM;

    // resident W for modes 1/2 (64KB)
    if (MODE != 0) {
        uint32_t wdst = smem_u32(smc);
#pragma unroll
        for (int j = 0; j < 16; j++) {
            int ch = j * THREADS + tid;
            cpa16(wdst + ch * 16, Wg + ch * 4);
        }
    }
    CP_COMMIT();
    if (MODE != 2 && tid < 128) ((float*)(smc + OFFB))[tid] = bias[tid];

    for (int t = blockIdx.x; t < ntiles; t += GRID) {
        const int rbase = t * BM;
        if (MODE == 1 && tid < BM) ((int*)(smc + OFFI))[tid] = g_idx[rbase + tid];

        issue_stage<MODE>(smc, 0, 0, tid, A0, Wg, rbase); CP_COMMIT();
        issue_stage<MODE>(smc, 1, 1, tid, A0, Wg, rbase); CP_COMMIT();

        float acc[2][8][4];
#pragma unroll
        for (int mt = 0; mt < 2; mt++)
#pragma unroll
            for (int nt = 0; nt < 8; nt++)
#pragma unroll
                for (int e = 0; e < 4; e++) acc[mt][nt][e] = 0.f;

#pragma unroll 1
        for (int c = 0; c < NCH; ++c) {
            CP_WAIT1();            // stage c landed (newest commit is stage c+1)
            __syncthreads();       // visible everywhere; chunk c-1 reads all done
            if (c + 2 < NCH)       // buf (c+2)%3 == (c-1)%3, safe after sync
                issue_stage<MODE>(smc, (c + 2) % 3, c + 2, tid, A0, Wg, rbase);
            else if (MODE == 1)    // c=2 -> z rows 0-63 into buf1; c=3 -> 64-127 into buf2
                issue_z(smc, (c + 2) % 3, (c - 2) * 64, tid);
            CP_COMMIT();           // uniform group counting

            const char* ab = (MODE == 0) ? smc + (c % 3) * STG0
                                         : smc + OFFA12 + (c % 3) * STG12;
            const char* wb = (MODE == 0) ? ab + 16384 : smc + c * 16384;
#pragma unroll
            for (int ks = 0; ks < 4; ks++) {
                uint32_t a[2][4];
#pragma unroll
                for (int mt = 0; mt < 2; mt++) {
                    const char* base = ab + (mrow + mt * 16 + g) * 128 + t4 * 4;
                    const int c0 = ((2 * ks) ^ g) * 16;
                    const int c1 = ((2 * ks + 1) ^ g) * 16;
                    if (MODE == 2) {    // g_y already exact tf32 -> skip cvt
                        a[mt][0] = *(const uint32_t*)(base + c0);
                        a[mt][1] = *(const uint32_t*)(base + 8 * 128 + c0);
                        a[mt][2] = *(const uint32_t*)(base + c1);
                        a[mt][3] = *(const uint32_t*)(base + 8 * 128 + c1);
                    } else {
                        a[mt][0] = rna_u(*(const float*)(base + c0));
                        a[mt][1] = rna_u(*(const float*)(base + 8 * 128 + c0));
                        a[mt][2] = rna_u(*(const float*)(base + c1));
                        a[mt][3] = rna_u(*(const float*)(base + 8 * 128 + c1));
                    }
                }
                uint4 bq[4];
#pragma unroll
                for (int i = 0; i < 4; i++)
                    bq[i] = *(const uint4*)(wb + ((ks * 8 + qbase + i) * 32 + lane) * 16);
#pragma unroll
                for (int mt = 0; mt < 2; mt++) {
#pragma unroll
                    for (int nt = 0; nt < 8; nt++) {
                        uint32_t b0 = (nt & 1) ? bq[nt >> 1].z : bq[nt >> 1].x;
                        uint32_t b1 = (nt & 1) ? bq[nt >> 1].w : bq[nt >> 1].y;
                        MMA_TF32(acc[mt][nt], a[mt], b0, b1);
                    }
                }
            }
        }

        // ---------------- epilogue ----------------
        if (MODE == 2) {
#pragma unroll
            for (int nt = 0; nt < 8; nt++) {
                const int col = ncol + nt * 8 + t4 * 2;
#pragma unroll
                for (int mt = 0; mt < 2; mt++) {
                    const int r0 = rbase + mrow + mt * 16 + g;
                    *(__half2*)(g_zh + (size_t)r0 * 128 + col) =
                        __floats2half2_rn(acc[mt][nt][0], acc[mt][nt][1]);
                    *(__half2*)(g_zh + (size_t)(r0 + 8) * 128 + col) =
                        __floats2half2_rn(acc[mt][nt][2], acc[mt][nt][3]);
                }
            }
        } else if (MODE == 1) {
            CP_WAIT0();            // z staging complete (groups from c=2,3)
            __syncthreads();       // visible to all warps
            const float* bs = (const float*)(smc + OFFB);
            const char* zb = smc + OFFA12 + STG12;   // buf1 (rows 0-63) + buf2 (64-127)
#pragma unroll
            for (int nt = 0; nt < 8; nt++) {
                const int col = ncol + nt * 8 + t4 * 2;
                const float b0 = bs[col], b1 = bs[col + 1];
#pragma unroll
                for (int mt = 0; mt < 2; mt++) {
                    const int lr0 = mrow + mt * 16 + g, lr1 = lr0 + 8;
                    const int r0 = rbase + lr0;
                    float2 z0 = __half22float2(*(const __half2*)(zb + lr0 * 256 +
                                   (((col >> 4) ^ (lr0 & 7)) << 5) + (col & 15) * 2));
                    float2 z1 = __half22float2(*(const __half2*)(zb + lr1 * 256 +
                                   (((col >> 4) ^ (lr1 & 7)) << 5) + (col & 15) * 2));
                    float2 v0, v1;
                    v0.x = lrelu(acc[mt][nt][0] + b0 + z0.x);
                    v0.y = lrelu(acc[mt][nt][1] + b1 + z0.y);
                    v1.x = lrelu(acc[mt][nt][2] + b0 + z1.x);
                    v1.y = lrelu(acc[mt][nt][3] + b1 + z1.y);
                    *(float2*)(out + (size_t)r0 * 128 + col) = v0;
                    *(float2*)(out + (size_t)(r0 + 8) * 128 + col) = v1;
                }
            }
        } else {   // MODE 0
            const float* bs = (const float*)(smc + OFFB);
#pragma unroll
            for (int nt = 0; nt < 8; nt++) {
                const int col = ncol + nt * 8 + t4 * 2;
                const float b0 = bs[col], b1 = bs[col + 1];
#pragma unroll
                for (int mt = 0; mt < 2; mt++) {
                    const int r0 = rbase + mrow + mt * 16 + g;
                    float2 v0, v1;
                    v0.x = tf32_rna(lrelu(acc[mt][nt][0] + b0));
                    v0.y = tf32_rna(lrelu(acc[mt][nt][1] + b1));
                    v1.x = tf32_rna(lrelu(acc[mt][nt][2] + b0));
                    v1.y = tf32_rna(lrelu(acc[mt][nt][3] + b1));
                    *(float2*)(out + (size_t)r0 * 128 + col) = v0;
                    *(float2*)(out + (size_t)(r0 + 8) * 128 + col) = v1;
                }
            }
        }
        __syncthreads();   // protect buffers/sIdx before next tile's prologue
    }
}

// ---------------- launch ----------------
extern "C" void kernel_launch(void* const* d_in, const int* in_sizes, int n_in,
                              void* d_out, int out_size) {
    const float* x_down = (const float*)d_in[0];
    const float* x_up   = (const float*)d_in[1];
    const void*  up_idx = d_in[2];
    const float* Wlin   = (const float*)d_in[3];
    const float* blin   = (const float*)d_in[4];
    const float* bfus   = (const float*)d_in[6];
    float* out = (float*)d_out;

    constexpr int SM0  = 3 * STG0 + 512 + 512;   //  99328
    constexpr int SM12 = OFFB12 + 512;           // 115712

    cudaFuncSetAttribute(gemm_tf32<0>, cudaFuncAttributeMaxDynamicSharedMemorySize, SM0);
    cudaFuncSetAttribute(gemm_tf32<1>, cudaFuncAttributeMaxDynamicSharedMemorySize, SM12);
    cudaFuncSetAttribute(gemm_tf32<2>, cudaFuncAttributeMaxDynamicSharedMemorySize, SM12);

    k_prep<<<1152, 256>>>(up_idx, Wlin, (const float*)d_in[5]);             // launch 1
    gemm_tf32<0><<<GRID, THREADS, SM0>>>(x_down, blin, nullptr);            // launch 2
    gemm_tf32<2><<<GRID, THREADS, SM12>>>(nullptr, nullptr, nullptr);       // launch 3
    gemm_tf32<1><<<GRID, THREADS, SM12>>>(x_up, bfus, out);                 // launch 4 (profiled)
}

// round 15
// speedup vs baseline: 2.5281x; 1.0554x over previous
#include <cuda_runtime.h>
#include <cuda_fp16.h>
#include <cstdint>

// ---------------- problem constants ----------------
#define N_DOWN  16384
#define M1 65536              // rows of x_down / z
#define M2 262144             // rows of x_up / out
#define BM 128
#define THREADS 256
#define GRID 296              // 2 CTAs per SM

// ---------------- device scratch ----------------
__device__ __align__(256) __half g_zh[(size_t)M1 * 128];  // f16(y @ Wfus_bot)
__device__ __align__(256) float  g_Wf1[32768];            // Wlin fragment-packed (K=256)
__device__ __align__(256) float  g_Wt[16384];             // Wfus[k<128]  fragment-packed
__device__ __align__(256) float  g_Wb[16384];             // Wfus[k>=128] fragment-packed
__device__ int g_idx[M2];

// smem geometry
#define STG0   32768                    // mode0 stage: [A 16KB | W 16KB]
#define STG12  16384                    // mode1 A stage
#define OFFA12 65536                    // mode1: resident W 64KB then A stages
#define OFFI12 (OFFA12 + 3 * STG12)     // 114688
#define OFFB12 (OFFI12 + 512)
#define OFFB0  (3 * STG0 + 512)         // mode0 bias (after unused idx slot)
// mode0 z-phase overlay: y tile fp16 at [0,32768); Wb slots at 32768 + s*16384

// ---------------- helpers ----------------
__device__ __forceinline__ float tf32_rna(float x) {
    unsigned u; asm("cvt.rna.tf32.f32 %0, %1;" : "=r"(u) : "f"(x));
    return __uint_as_float(u);
}
__device__ __forceinline__ uint32_t rna_u(float x) {
    unsigned u; asm("cvt.rna.tf32.f32 %0, %1;" : "=r"(u) : "f"(x));
    return u;
}
__device__ __forceinline__ float lrelu(float v) { return v > 0.f ? v : 0.1f * v; }

__device__ __forceinline__ uint32_t smem_u32(const void* p) {
    uint32_t a;
    asm("{ .reg .u64 t; cvta.to.shared.u64 t, %1; cvt.u32.u64 %0, t; }" : "=r"(a) : "l"(p));
    return a;
}
__device__ __forceinline__ void cpa16(uint32_t saddr, const void* g) {
    asm volatile("cp.async.cg.shared.global [%0], [%1], 16;" :: "r"(saddr), "l"(g));
}
#define CP_COMMIT() asm volatile("cp.async.commit_group;" ::: "memory")
#define CP_WAIT1()  asm volatile("cp.async.wait_group 1;" ::: "memory")
#define CP_WAIT0()  asm volatile("cp.async.wait_group 0;" ::: "memory")

#define MMA_TF32(d, a, b0, b1)                                                     \
    asm volatile(                                                                  \
        "mma.sync.aligned.m16n8k8.row.col.f32.tf32.tf32.f32 "                      \
        "{%0,%1,%2,%3},{%4,%5,%6,%7},{%8,%9},{%0,%1,%2,%3};"                       \
        : "+f"((d)[0]), "+f"((d)[1]), "+f"((d)[2]), "+f"((d)[3])                   \
        : "r"((a)[0]), "r"((a)[1]), "r"((a)[2]), "r"((a)[3]), "r"(b0), "r"(b1))

// ---------------- merged prep kernel ----------------
__global__ void k_prep(const void* __restrict__ p,
                       const float* __restrict__ Wlin,
                       const float* __restrict__ Wfus) {
    const int b = blockIdx.x;
    if (b < 1024) {
        __shared__ unsigned red[256];
        const int i = b * 256 + threadIdx.x;
        const int j = i & (M2 / 2 - 1);
        red[threadIdx.x] = ((const unsigned*)p)[2 * j + 1];
        __syncthreads();
        for (int s = 128; s > 0; s >>= 1) {
            if ((int)threadIdx.x < s) red[threadIdx.x] |= red[threadIdx.x + s];
            __syncthreads();
        }
        const int is64 = (red[0] == 0u);
        int v = is64 ? (int)((const long long*)p)[i] : ((const int*)p)[i];
        g_idx[i] = (i >> 16) * N_DOWN + v;   // batch = i / 65536
    } else {
        int i = (b - 1024) * 256 + threadIdx.x;   // 0..32767
        int e = i & 3, lane = (i >> 2) & 31, q = (i >> 7) & 7, kk = i >> 10;
        int pp = e >> 1, hb = e & 1;
        int n = (2 * q + pp) * 8 + (lane >> 2);
        int k = kk * 8 + (lane & 3) + hb * 4;
        g_Wf1[i] = tf32_rna(Wlin[k * 128 + n]);
        if (i < 16384) {
            g_Wt[i] = tf32_rna(Wfus[k * 128 + n]);
            g_Wb[i] = tf32_rna(Wfus[(k + 128) * 128 + n]);
        }
    }
}

// ---------------- persistent tf32 GEMMs ----------------
// MODE 0 (fused): per tile: acc = x_down@Wlin (K=256, streamed Wlin);
//                 y=f16(lrelu(acc+b)) -> smem; z = y@Wfus_bot (K=128, streamed Wb);
//                 g_zh = f16(z).   y never touches gmem.
// MODE 1: out = LReLU(x_up@Wfus_top + b + gather(g_zh))  K=128, resident W
template <int MODE>
__device__ __forceinline__ void issue_stage(char* smc, int buf, int c, int tid,
                                            const float* __restrict__ A0,
                                            const float* __restrict__ Wg, int rbase) {
    constexpr int KSTR = (MODE == 0) ? 256 : 128;
    const int row = tid >> 1, half = tid & 1;
    const float* src = A0 + (size_t)(rbase + row) * KSTR + c * 32 + half * 16;
    uint32_t abuf = (MODE == 0)
        ? smem_u32(smc) + buf * STG0 + row * 128
        : smem_u32(smc) + OFFA12 + buf * STG12 + row * 128;
    const int cb = half * 4, sw = row & 7;
#pragma unroll
    for (int j = 0; j < 4; j++)
        cpa16(abuf + ((cb + j) ^ sw) * 16, src + j * 4);
    if (MODE == 0) {   // stream 16KB Wlin chunk alongside A
        uint32_t wbuf = smem_u32(smc) + buf * STG0 + 16384;
        const float* wsrc = Wg + c * 4096;
#pragma unroll
        for (int j = 0; j < 4; j++) {
            int ch = j * THREADS + tid;
            cpa16(wbuf + ch * 16, wsrc + ch * 4);
        }
    }
}

// Stream one 16KB Wb fragment chunk into slot s (overlay at 32768 + s*16384)
__device__ __forceinline__ void issue_wb(char* smc, int slot, int c, int tid) {
    uint32_t wbuf = smem_u32(smc) + 32768 + slot * 16384;
    const float* wsrc = g_Wb + c * 4096;
#pragma unroll
    for (int j = 0; j < 4; j++) {
        int ch = j * THREADS + tid;
        cpa16(wbuf + ch * 16, wsrc + ch * 4);
    }
}

// Prefetch 64 fp16 z-rows into mode1 A buffer `buf` (16KB); 32B-granule swizzle.
__device__ __forceinline__ void issue_z(char* smc, int buf, int rowbase, int tid) {
    const int rr = tid >> 2;
    const int seg = tid & 3;
    const int gr = ((const int*)(smc + OFFI12))[rowbase + rr];
    const char* src = (const char*)(g_zh + (size_t)gr * 128) + seg * 64;
    uint32_t base = smem_u32(smc) + OFFA12 + buf * STG12 + rr * 256;
    const int sw = rr & 7;
#pragma unroll
    for (int j = 0; j < 4; j++) {
        int c0 = seg * 4 + j;
        int u = (c0 >> 1) ^ sw;
        cpa16(base + u * 32 + (c0 & 1) * 16, src + j * 16);
    }
}

template <int MODE>
__global__ void __launch_bounds__(THREADS, 2)
gemm_tf32(const float* __restrict__ A0, const float* __restrict__ bias,
          float* __restrict__ outp) {
    constexpr int NCH  = (MODE == 0) ? 8 : 4;
    constexpr int OFFB = (MODE == 0) ? OFFB0 : OFFB12;

    extern __shared__ char smc[];
    const int tid = threadIdx.x;
    const int lane = tid & 31, wid = tid >> 5;
    const int g = lane >> 2, t4 = lane & 3;
    const int mrow = (wid & 3) * 32;          // warp tile 32x64 (4x2 warp grid)
    const int ncol = (wid >> 2) * 64;
    const int qbase = ncol >> 4;

    const float* Wg = (MODE == 0) ? g_Wf1 : g_Wt;
    const int ntiles = ((MODE == 1) ? M2 : M1) / BM;

    if (MODE == 1) {   // resident W top (64KB)
        uint32_t wdst = smem_u32(smc);
#pragma unroll
        for (int j = 0; j < 16; j++) {
            int ch = j * THREADS + tid;
            cpa16(wdst + ch * 16, Wg + ch * 4);
        }
    }
    CP_COMMIT();
    if (tid < 128) ((float*)(smc + OFFB))[tid] = bias[tid];

    for (int t = blockIdx.x; t < ntiles; t += GRID) {
        const int rbase = t * BM;
        if (MODE == 1 && tid < BM) ((int*)(smc + OFFI12))[tid] = g_idx[rbase + tid];

        issue_stage<MODE>(smc, 0, 0, tid, A0, Wg, rbase); CP_COMMIT();
        issue_stage<MODE>(smc, 1, 1, tid, A0, Wg, rbase); CP_COMMIT();

        float acc[2][8][4];
#pragma unroll
        for (int mt = 0; mt < 2; mt++)
#pragma unroll
            for (int nt = 0; nt < 8; nt++)
#pragma unroll
                for (int e = 0; e < 4; e++) acc[mt][nt][e] = 0.f;

#pragma unroll 1
        for (int c = 0; c < NCH; ++c) {
            CP_WAIT1();
            __syncthreads();
            if (c + 2 < NCH)
                issue_stage<MODE>(smc, (c + 2) % 3, c + 2, tid, A0, Wg, rbase);
            else if (MODE == 1)
                issue_z(smc, (c + 2) % 3, (c - 2) * 64, tid);
            CP_COMMIT();

            const char* ab = (MODE == 0) ? smc + (c % 3) * STG0
                                         : smc + OFFA12 + (c % 3) * STG12;
            const char* wb = (MODE == 0) ? ab + 16384 : smc + c * 16384;
#pragma unroll
            for (int ks = 0; ks < 4; ks++) {
                uint32_t a[2][4];
#pragma unroll
                for (int mt = 0; mt < 2; mt++) {
                    const char* base = ab + (mrow + mt * 16 + g) * 128 + t4 * 4;
                    const int c0 = ((2 * ks) ^ g) * 16;
                    const int c1 = ((2 * ks + 1) ^ g) * 16;
                    a[mt][0] = rna_u(*(const float*)(base + c0));
                    a[mt][1] = rna_u(*(const float*)(base + 8 * 128 + c0));
                    a[mt][2] = rna_u(*(const float*)(base + c1));
                    a[mt][3] = rna_u(*(const float*)(base + 8 * 128 + c1));
                }
                uint4 bq[4];
#pragma unroll
                for (int i = 0; i < 4; i++)
                    bq[i] = *(const uint4*)(wb + ((ks * 8 + qbase + i) * 32 + lane) * 16);
#pragma unroll
                for (int mt = 0; mt < 2; mt++) {
#pragma unroll
                    for (int nt = 0; nt < 8; nt++) {
                        uint32_t b0 = (nt & 1) ? bq[nt >> 1].z : bq[nt >> 1].x;
                        uint32_t b1 = (nt & 1) ? bq[nt >> 1].w : bq[nt >> 1].y;
                        MMA_TF32(acc[mt][nt], a[mt], b0, b1);
                    }
                }
            }
        }

        if (MODE == 0) {
            // ---- epilogue1: y = f16(lrelu(acc+b)) -> smem [0,32KB); start Wb stream
            __syncthreads();                       // all mainloop reads done
            issue_wb(smc, 0, 0, tid); CP_COMMIT();
            {
                const float* bs = (const float*)(smc + OFFB);
#pragma unroll
                for (int nt = 0; nt < 8; nt++) {
                    const int col = ncol + nt * 8 + t4 * 2;
                    const float b0 = bs[col], b1 = bs[col + 1];
#pragma unroll
                    for (int mt = 0; mt < 2; mt++) {
                        const int r0 = mrow + mt * 16 + g, r1 = r0 + 8;
                        __half2 h0 = __floats2half2_rn(lrelu(acc[mt][nt][0] + b0),
                                                       lrelu(acc[mt][nt][1] + b1));
                        __half2 h1 = __floats2half2_rn(lrelu(acc[mt][nt][2] + b0),
                                                       lrelu(acc[mt][nt][3] + b1));
                        *(__half2*)(smc + r0 * 256 + (((col >> 3) ^ (r0 & 7)) << 4) + t4 * 4) = h0;
                        *(__half2*)(smc + r1 * 256 + (((col >> 3) ^ (r1 & 7)) << 4) + t4 * 4) = h1;
                    }
                }
            }
            issue_wb(smc, 1, 1, tid); CP_COMMIT();
            __syncthreads();                       // y visible everywhere

            // ---- z-phase: z = y @ Wfus_bot (4 chunks, 2-slot Wb pipeline)
            float zac[2][8][4];
#pragma unroll
            for (int mt = 0; mt < 2; mt++)
#pragma unroll
                for (int nt = 0; nt < 8; nt++)
#pragma unroll
                    for (int e = 0; e < 4; e++) zac[mt][nt][e] = 0.f;

#pragma unroll 1
            for (int c = 0; c < 4; ++c) {
                CP_WAIT1();
                __syncthreads();
                const char* wb = smc + 32768 + (c & 1) * 16384;
#pragma unroll
                for (int ks = 0; ks < 4; ks++) {
                    uint32_t a[2][4];
#pragma unroll
                    for (int mt = 0; mt < 2; mt++) {
                        const int r0 = mrow + mt * 16 + g;
                        const char* y0 = smc + r0 * 256 + (((c * 4 + ks) ^ g) << 4);
                        const char* y1 = y0 + 8 * 256;
                        a[mt][0] = __float_as_uint(__half2float(*(const __half*)(y0 + t4 * 2)));
                        a[mt][1] = __float_as_uint(__half2float(*(const __half*)(y1 + t4 * 2)));
                        a[mt][2] = __float_as_uint(__half2float(*(const __half*)(y0 + 8 + t4 * 2)));
                        a[mt][3] = __float_as_uint(__half2float(*(const __half*)(y1 + 8 + t4 * 2)));
                    }
                    uint4 bq[4];
#pragma unroll
                    for (int i = 0; i < 4; i++)
                        bq[i] = *(const uint4*)(wb + ((ks * 8 + qbase + i) * 32 + lane) * 16);
#pragma unroll
                    for (int mt = 0; mt < 2; mt++) {
#pragma unroll
                        for (int nt = 0; nt < 8; nt++) {
                            uint32_t b0 = (nt & 1) ? bq[nt >> 1].z : bq[nt >> 1].x;
                            uint32_t b1 = (nt & 1) ? bq[nt >> 1].w : bq[nt >> 1].y;
                            MMA_TF32(zac[mt][nt], a[mt], b0, b1);
                        }
                    }
                }
                __syncthreads();                   // slot reads done
                if (c + 2 < 4) issue_wb(smc, c & 1, c + 2, tid);
                CP_COMMIT();
            }

            // ---- epilogue2: g_zh = f16(z)
#pragma unroll
            for (int nt = 0; nt < 8; nt++) {
                const int col = ncol + nt * 8 + t4 * 2;
#pragma unroll
                for (int mt = 0; mt < 2; mt++) {
                    const int r0 = rbase + mrow + mt * 16 + g;
                    *(__half2*)(g_zh + (size_t)r0 * 128 + col) =
                        __floats2half2_rn(zac[mt][nt][0], zac[mt][nt][1]);
                    *(__half2*)(g_zh + (size_t)(r0 + 8) * 128 + col) =
                        __floats2half2_rn(zac[mt][nt][2], zac[mt][nt][3]);
                }
            }
        } else {
            // ---- MODE 1 epilogue: bias + z-gather(smem) + LReLU
            CP_WAIT0();
            __syncthreads();
            const float* bs = (const float*)(smc + OFFB);
            const char* zb = smc + OFFA12 + STG12;
#pragma unroll
            for (int nt = 0; nt < 8; nt++) {
                const int col = ncol + nt * 8 + t4 * 2;
                const float b0 = bs[col], b1 = bs[col + 1];
#pragma unroll
                for (int mt = 0; mt < 2; mt++) {
                    const int lr0 = mrow + mt * 16 + g, lr1 = lr0 + 8;
                    const int r0 = rbase + lr0;
                    float2 z0 = __half22float2(*(const __half2*)(zb + lr0 * 256 +
                                   (((col >> 4) ^ (lr0 & 7)) << 5) + (col & 15) * 2));
                    float2 z1 = __half22float2(*(const __half2*)(zb + lr1 * 256 +
                                   (((col >> 4) ^ (lr1 & 7)) << 5) + (col & 15) * 2));
                    float2 v0, v1;
                    v0.x = lrelu(acc[mt][nt][0] + b0 + z0.x);
                    v0.y = lrelu(acc[mt][nt][1] + b1 + z0.y);
                    v1.x = lrelu(acc[mt][nt][2] + b0 + z1.x);
                    v1.y = lrelu(acc[mt][nt][3] + b1 + z1.y);
                    *(float2*)(outp + (size_t)r0 * 128 + col) = v0;
                    *(float2*)(outp + (size_t)(r0 + 8) * 128 + col) = v1;
                }
            }
        }
        __syncthreads();   // protect buffers/sIdx before next tile's prologue
    }
}

// ---------------- launch ----------------
extern "C" void kernel_launch(void* const* d_in, const int* in_sizes, int n_in,
                              void* d_out, int out_size) {
    const float* x_down = (const float*)d_in[0];
    const float* x_up   = (const float*)d_in[1];
    const void*  up_idx = d_in[2];
    const float* Wlin   = (const float*)d_in[3];
    const float* blin   = (const float*)d_in[4];
    const float* bfus   = (const float*)d_in[6];
    float* out = (float*)d_out;

    constexpr int SM0  = OFFB0 + 512;    //  99328
    constexpr int SM12 = OFFB12 + 512;   // 115712

    cudaFuncSetAttribute(gemm_tf32<0>, cudaFuncAttributeMaxDynamicSharedMemorySize, SM0);
    cudaFuncSetAttribute(gemm_tf32<1>, cudaFuncAttributeMaxDynamicSharedMemorySize, SM12);

    k_prep<<<1152, 256>>>(up_idx, Wlin, (const float*)d_in[5]);     // launch 1
    gemm_tf32<0><<<GRID, THREADS, SM0>>>(x_down, blin, nullptr);    // launch 2 (fused y+z)
    gemm_tf32<1><<<GRID, THREADS, SM12>>>(x_up, bfus, out);         // launch 3
}

// round 16
// speedup vs baseline: 2.5343x; 1.0025x over previous
#include <cuda_runtime.h>
#include <cuda_fp16.h>
#include <cstdint>

// ---------------- problem constants ----------------
#define N_DOWN  16384
#define M1 65536              // rows of x_down / z
#define M2 262144             // rows of x_up / out
#define BM 128
#define THREADS 256
#define GRID 296              // 2 CTAs per SM

// ---------------- device scratch ----------------
__device__ __align__(256) __half g_zh[(size_t)M1 * 128];  // f16(y @ Wfus_bot)
__device__ __align__(256) float  g_Wf1[32768];            // Wlin fragment-packed (K=256)
__device__ __align__(256) float  g_Wt[16384];             // Wfus[k<128]  fragment-packed
__device__ __align__(256) float  g_Wb[16384];             // Wfus[k>=128] fragment-packed
__device__ int g_idx[M2];

// smem geometry
#define STG0   32768                    // mode0 stage: [A 16KB | W 16KB]
#define STG12  16384                    // mode1 A stage
#define OFFA12 65536                    // mode1: resident W 64KB then A stages
#define OFFI12 (OFFA12 + 3 * STG12)     // 114688
#define OFFB12 (OFFI12 + 512)
#define OFFB0  (3 * STG0 + 512)         // mode0 bias (after unused idx slot)
// mode0 z-phase overlay: y tile fp16 at [0,32768); Wb slots at 32768 + s*16384

// ---------------- helpers ----------------
__device__ __forceinline__ float tf32_rna(float x) {
    unsigned u; asm("cvt.rna.tf32.f32 %0, %1;" : "=r"(u) : "f"(x));
    return __uint_as_float(u);
}
__device__ __forceinline__ uint32_t rna_u(float x) {
    unsigned u; asm("cvt.rna.tf32.f32 %0, %1;" : "=r"(u) : "f"(x));
    return u;
}
__device__ __forceinline__ float lrelu(float v) { return v > 0.f ? v : 0.1f * v; }

__device__ __forceinline__ uint32_t smem_u32(const void* p) {
    uint32_t a;
    asm("{ .reg .u64 t; cvta.to.shared.u64 t, %1; cvt.u32.u64 %0, t; }" : "=r"(a) : "l"(p));
    return a;
}
__device__ __forceinline__ void cpa16(uint32_t saddr, const void* g) {
    asm volatile("cp.async.cg.shared.global [%0], [%1], 16;" :: "r"(saddr), "l"(g));
}
#define CP_COMMIT() asm volatile("cp.async.commit_group;" ::: "memory")
#define CP_WAIT1()  asm volatile("cp.async.wait_group 1;" ::: "memory")
#define CP_WAIT0()  asm volatile("cp.async.wait_group 0;" ::: "memory")

#define MMA_TF32(d, a, b0, b1)                                                     \
    asm volatile(                                                                  \
        "mma.sync.aligned.m16n8k8.row.col.f32.tf32.tf32.f32 "                      \
        "{%0,%1,%2,%3},{%4,%5,%6,%7},{%8,%9},{%0,%1,%2,%3};"                       \
        : "+f"((d)[0]), "+f"((d)[1]), "+f"((d)[2]), "+f"((d)[3])                   \
        : "r"((a)[0]), "r"((a)[1]), "r"((a)[2]), "r"((a)[3]), "r"(b0), "r"(b1))

// ---------------- merged prep kernel ----------------
__global__ void k_prep(const void* __restrict__ p,
                       const float* __restrict__ Wlin,
                       const float* __restrict__ Wfus) {
    const int b = blockIdx.x;
    if (b < 1024) {
        __shared__ unsigned red[256];
        const int i = b * 256 + threadIdx.x;
        const int j = i & (M2 / 2 - 1);
        red[threadIdx.x] = ((const unsigned*)p)[2 * j + 1];
        __syncthreads();
        for (int s = 128; s > 0; s >>= 1) {
            if ((int)threadIdx.x < s) red[threadIdx.x] |= red[threadIdx.x + s];
            __syncthreads();
        }
        const int is64 = (red[0] == 0u);
        int v = is64 ? (int)((const long long*)p)[i] : ((const int*)p)[i];
        g_idx[i] = (i >> 16) * N_DOWN + v;   // batch = i / 65536
    } else {
        int i = (b - 1024) * 256 + threadIdx.x;   // 0..32767
        int e = i & 3, lane = (i >> 2) & 31, q = (i >> 7) & 7, kk = i >> 10;
        int pp = e >> 1, hb = e & 1;
        int n = (2 * q + pp) * 8 + (lane >> 2);
        int k = kk * 8 + (lane & 3) + hb * 4;
        g_Wf1[i] = tf32_rna(Wlin[k * 128 + n]);
        if (i < 16384) {
            g_Wt[i] = tf32_rna(Wfus[k * 128 + n]);
            g_Wb[i] = tf32_rna(Wfus[(k + 128) * 128 + n]);
        }
    }
}

// ---------------- persistent tf32 GEMMs ----------------
// MODE 0 (fused): per tile: acc = x_down@Wlin (K=256, streamed Wlin);
//                 y=f16(lrelu(acc+b)) -> smem; z = y@Wfus_bot (K=128, streamed Wb);
//                 g_zh = f16(z).   y never touches gmem.
// MODE 1: out = LReLU(x_up@Wfus_top + b + gather(g_zh))  K=128, resident W
template <int MODE>
__device__ __forceinline__ void issue_stage(char* smc, int buf, int c, int tid,
                                            const float* __restrict__ A0,
                                            const float* __restrict__ Wg, int rbase) {
    constexpr int KSTR = (MODE == 0) ? 256 : 128;
    const int row = tid >> 1, half = tid & 1;
    const float* src = A0 + (size_t)(rbase + row) * KSTR + c * 32 + half * 16;
    uint32_t abuf = (MODE == 0)
        ? smem_u32(smc) + buf * STG0 + row * 128
        : smem_u32(smc) + OFFA12 + buf * STG12 + row * 128;
    const int cb = half * 4, sw = row & 7;
#pragma unroll
    for (int j = 0; j < 4; j++)
        cpa16(abuf + ((cb + j) ^ sw) * 16, src + j * 4);
    if (MODE == 0) {   // stream 16KB Wlin chunk alongside A
        uint32_t wbuf = smem_u32(smc) + buf * STG0 + 16384;
        const float* wsrc = Wg + c * 4096;
#pragma unroll
        for (int j = 0; j < 4; j++) {
            int ch = j * THREADS + tid;
            cpa16(wbuf + ch * 16, wsrc + ch * 4);
        }
    }
}

// Stream one 16KB Wb fragment chunk into slot s (overlay at 32768 + s*16384)
__device__ __forceinline__ void issue_wb(char* smc, int slot, int c, int tid) {
    uint32_t wbuf = smem_u32(smc) + 32768 + slot * 16384;
    const float* wsrc = g_Wb + c * 4096;
#pragma unroll
    for (int j = 0; j < 4; j++) {
        int ch = j * THREADS + tid;
        cpa16(wbuf + ch * 16, wsrc + ch * 4);
    }
}

// Prefetch 64 fp16 z-rows into mode1 A buffer `buf` (16KB); 32B-granule swizzle.
__device__ __forceinline__ void issue_z(char* smc, int buf, int rowbase, int tid) {
    const int rr = tid >> 2;
    const int seg = tid & 3;
    const int gr = ((const int*)(smc + OFFI12))[rowbase + rr];
    const char* src = (const char*)(g_zh + (size_t)gr * 128) + seg * 64;
    uint32_t base = smem_u32(smc) + OFFA12 + buf * STG12 + rr * 256;
    const int sw = rr & 7;
#pragma unroll
    for (int j = 0; j < 4; j++) {
        int c0 = seg * 4 + j;
        int u = (c0 >> 1) ^ sw;
        cpa16(base + u * 32 + (c0 & 1) * 16, src + j * 16);
    }
}

template <int MODE>
__global__ void __launch_bounds__(THREADS, 2)
gemm_tf32(const float* __restrict__ A0, const float* __restrict__ bias,
          float* __restrict__ outp) {
    constexpr int NCH  = (MODE == 0) ? 8 : 4;
    constexpr int OFFB = (MODE == 0) ? OFFB0 : OFFB12;

    extern __shared__ char smc[];
    const int tid = threadIdx.x;
    const int lane = tid & 31, wid = tid >> 5;
    const int g = lane >> 2, t4 = lane & 3;
    const int mrow = (wid & 3) * 32;          // warp tile 32x64 (4x2 warp grid)
    const int ncol = (wid >> 2) * 64;
    const int qbase = ncol >> 4;

    const float* Wg = (MODE == 0) ? g_Wf1 : g_Wt;
    const int ntiles = ((MODE == 1) ? M2 : M1) / BM;

    if (MODE == 1) {   // resident W top (64KB)
        uint32_t wdst = smem_u32(smc);
#pragma unroll
        for (int j = 0; j < 16; j++) {
            int ch = j * THREADS + tid;
            cpa16(wdst + ch * 16, Wg + ch * 4);
        }
    }
    CP_COMMIT();
    if (tid < 128) ((float*)(smc + OFFB))[tid] = bias[tid];

    for (int t = blockIdx.x; t < ntiles; t += GRID) {
        const int rbase = t * BM;
        if (MODE == 1 && tid < BM) ((int*)(smc + OFFI12))[tid] = g_idx[rbase + tid];

        issue_stage<MODE>(smc, 0, 0, tid, A0, Wg, rbase); CP_COMMIT();
        issue_stage<MODE>(smc, 1, 1, tid, A0, Wg, rbase); CP_COMMIT();

        float acc[2][8][4];
#pragma unroll
        for (int mt = 0; mt < 2; mt++)
#pragma unroll
            for (int nt = 0; nt < 8; nt++)
#pragma unroll
                for (int e = 0; e < 4; e++) acc[mt][nt][e] = 0.f;

#pragma unroll 1
        for (int c = 0; c < NCH; ++c) {
            CP_WAIT1();
            __syncthreads();
            if (c + 2 < NCH)
                issue_stage<MODE>(smc, (c + 2) % 3, c + 2, tid, A0, Wg, rbase);
            else if (MODE == 1)
                issue_z(smc, (c + 2) % 3, (c - 2) * 64, tid);
            CP_COMMIT();

            const char* ab = (MODE == 0) ? smc + (c % 3) * STG0
                                         : smc + OFFA12 + (c % 3) * STG12;
            const char* wb = (MODE == 0) ? ab + 16384 : smc + c * 16384;
#pragma unroll
            for (int ks = 0; ks < 4; ks++) {
                uint32_t a[2][4];
#pragma unroll
                for (int mt = 0; mt < 2; mt++) {
                    const char* base = ab + (mrow + mt * 16 + g) * 128 + t4 * 4;
                    const int c0 = ((2 * ks) ^ g) * 16;
                    const int c1 = ((2 * ks + 1) ^ g) * 16;
                    a[mt][0] = rna_u(*(const float*)(base + c0));
                    a[mt][1] = rna_u(*(const float*)(base + 8 * 128 + c0));
                    a[mt][2] = rna_u(*(const float*)(base + c1));
                    a[mt][3] = rna_u(*(const float*)(base + 8 * 128 + c1));
                }
                uint4 bq[4];
#pragma unroll
                for (int i = 0; i < 4; i++)
                    bq[i] = *(const uint4*)(wb + ((ks * 8 + qbase + i) * 32 + lane) * 16);
#pragma unroll
                for (int mt = 0; mt < 2; mt++) {
#pragma unroll
                    for (int nt = 0; nt < 8; nt++) {
                        uint32_t b0 = (nt & 1) ? bq[nt >> 1].z : bq[nt >> 1].x;
                        uint32_t b1 = (nt & 1) ? bq[nt >> 1].w : bq[nt >> 1].y;
                        MMA_TF32(acc[mt][nt], a[mt], b0, b1);
                    }
                }
            }
        }

        if (MODE == 0) {
            // ---- epilogue1: y = f16(lrelu(acc+b)) -> smem [0,32KB); start Wb stream
            __syncthreads();                       // all mainloop reads done
            issue_wb(smc, 0, 0, tid); CP_COMMIT();
            {
                const float* bs = (const float*)(smc + OFFB);
#pragma unroll
                for (int nt = 0; nt < 8; nt++) {
                    const int col = ncol + nt * 8 + t4 * 2;
                    const float b0 = bs[col], b1 = bs[col + 1];
#pragma unroll
                    for (int mt = 0; mt < 2; mt++) {
                        const int r0 = mrow + mt * 16 + g, r1 = r0 + 8;
                        __half2 h0 = __floats2half2_rn(lrelu(acc[mt][nt][0] + b0),
                                                       lrelu(acc[mt][nt][1] + b1));
                        __half2 h1 = __floats2half2_rn(lrelu(acc[mt][nt][2] + b0),
                                                       lrelu(acc[mt][nt][3] + b1));
                        *(__half2*)(smc + r0 * 256 + (((col >> 3) ^ (r0 & 7)) << 4) + t4 * 4) = h0;
                        *(__half2*)(smc + r1 * 256 + (((col >> 3) ^ (r1 & 7)) << 4) + t4 * 4) = h1;
                    }
                }
            }
            issue_wb(smc, 1, 1, tid); CP_COMMIT();
            __syncthreads();                       // y visible everywhere

            // ---- z-phase: z = y @ Wfus_bot (4 chunks, 2-slot Wb pipeline)
            float zac[2][8][4];
#pragma unroll
            for (int mt = 0; mt < 2; mt++)
#pragma unroll
                for (int nt = 0; nt < 8; nt++)
#pragma unroll
                    for (int e = 0; e < 4; e++) zac[mt][nt][e] = 0.f;

#pragma unroll 1
            for (int c = 0; c < 4; ++c) {
                CP_WAIT1();
                __syncthreads();
                const char* wb = smc + 32768 + (c & 1) * 16384;
#pragma unroll
                for (int ks = 0; ks < 4; ks++) {
                    uint32_t a[2][4];
#pragma unroll
                    for (int mt = 0; mt < 2; mt++) {
                        const int r0 = mrow + mt * 16 + g;
                        const char* y0 = smc + r0 * 256 + (((c * 4 + ks) ^ g) << 4);
                        const char* y1 = y0 + 8 * 256;
                        a[mt][0] = __float_as_uint(__half2float(*(const __half*)(y0 + t4 * 2)));
                        a[mt][1] = __float_as_uint(__half2float(*(const __half*)(y1 + t4 * 2)));
                        a[mt][2] = __float_as_uint(__half2float(*(const __half*)(y0 + 8 + t4 * 2)));
                        a[mt][3] = __float_as_uint(__half2float(*(const __half*)(y1 + 8 + t4 * 2)));
                    }
                    uint4 bq[4];
#pragma unroll
                    for (int i = 0; i < 4; i++)
                        bq[i] = *(const uint4*)(wb + ((ks * 8 + qbase + i) * 32 + lane) * 16);
#pragma unroll
                    for (int mt = 0; mt < 2; mt++) {
#pragma unroll
                        for (int nt = 0; nt < 8; nt++) {
                            uint32_t b0 = (nt & 1) ? bq[nt >> 1].z : bq[nt >> 1].x;
                            uint32_t b1 = (nt & 1) ? bq[nt >> 1].w : bq[nt >> 1].y;
                            MMA_TF32(zac[mt][nt], a[mt], b0, b1);
                        }
                    }
                }
                __syncthreads();                   // slot reads done
                if (c + 2 < 4) issue_wb(smc, c & 1, c + 2, tid);
                CP_COMMIT();
            }

            // ---- epilogue2: g_zh = f16(z)
#pragma unroll
            for (int nt = 0; nt < 8; nt++) {
                const int col = ncol + nt * 8 + t4 * 2;
#pragma unroll
                for (int mt = 0; mt < 2; mt++) {
                    const int r0 = rbase + mrow + mt * 16 + g;
                    *(__half2*)(g_zh + (size_t)r0 * 128 + col) =
                        __floats2half2_rn(zac[mt][nt][0], zac[mt][nt][1]);
                    *(__half2*)(g_zh + (size_t)(r0 + 8) * 128 + col) =
                        __floats2half2_rn(zac[mt][nt][2], zac[mt][nt][3]);
                }
            }
        } else {
            // ---- MODE 1 epilogue: bias + z-gather(smem) + LReLU
            CP_WAIT0();
            __syncthreads();
            const float* bs = (const float*)(smc + OFFB);
            const char* zb = smc + OFFA12 + STG12;
#pragma unroll
            for (int nt = 0; nt < 8; nt++) {
                const int col = ncol + nt * 8 + t4 * 2;
                const float b0 = bs[col], b1 = bs[col + 1];
#pragma unroll
                for (int mt = 0; mt < 2; mt++) {
                    const int lr0 = mrow + mt * 16 + g, lr1 = lr0 + 8;
                    const int r0 = rbase + lr0;
                    float2 z0 = __half22float2(*(const __half2*)(zb + lr0 * 256 +
                                   (((col >> 4) ^ (lr0 & 7)) << 5) + (col & 15) * 2));
                    float2 z1 = __half22float2(*(const __half2*)(zb + lr1 * 256 +
                                   (((col >> 4) ^ (lr1 & 7)) << 5) + (col & 15) * 2));
                    float2 v0, v1;
                    v0.x = lrelu(acc[mt][nt][0] + b0 + z0.x);
                    v0.y = lrelu(acc[mt][nt][1] + b1 + z0.y);
                    v1.x = lrelu(acc[mt][nt][2] + b0 + z1.x);
                    v1.y = lrelu(acc[mt][nt][3] + b1 + z1.y);
                    *(float2*)(outp + (size_t)r0 * 128 + col) = v0;
                    *(float2*)(outp + (size_t)(r0 + 8) * 128 + col) = v1;
                }
            }
        }
        __syncthreads();   // protect buffers/sIdx before next tile's prologue
    }
}

// ---------------- launch ----------------
extern "C" void kernel_launch(void* const* d_in, const int* in_sizes, int n_in,
                              void* d_out, int out_size) {
    const float* x_down = (const float*)d_in[0];
    const float* x_up   = (const float*)d_in[1];
    const void*  up_idx = d_in[2];
    const float* Wlin   = (const float*)d_in[3];
    const float* blin   = (const float*)d_in[4];
    const float* bfus   = (const float*)d_in[6];
    float* out = (float*)d_out;

    constexpr int SM0  = OFFB0 + 512;    //  99328
    constexpr int SM12 = OFFB12 + 512;   // 115712

    cudaFuncSetAttribute(gemm_tf32<0>, cudaFuncAttributeMaxDynamicSharedMemorySize, SM0);
    cudaFuncSetAttribute(gemm_tf32<1>, cudaFuncAttributeMaxDynamicSharedMemorySize, SM12);

    k_prep<<<1152, 256>>>(up_idx, Wlin, (const float*)d_in[5]);     // launch 1
    gemm_tf32<0><<<GRID, THREADS, SM0>>>(x_down, blin, nullptr);    // launch 2 (fused y+z)
    gemm_tf32<1><<<GRID, THREADS, SM12>>>(x_up, bfus, out);         // launch 3
}